// round 1
// baseline (speedup 1.0000x reference)
#include <cuda_runtime.h>
#include <math.h>

#define BB   4
#define SS   1024
#define DDIM 1024
#define HH   16
#define DHH  64
#define FF   4096
#define MM   (BB*SS)      // 4096 rows
#define NEGV (-1e20f)

// ---------------- scratch (allocation-free: device globals) ----------------
__device__ float g_q  [MM*DDIM];
__device__ float g_k  [MM*DDIM];
__device__ float g_v  [MM*DDIM];
__device__ float g_ctx[MM*DDIM];
__device__ float g_y1 [MM*DDIM];
__device__ float g_t  [MM*DDIM];
__device__ float g_h  [(size_t)MM*FF];
__device__ float g_y2 [MM*DDIM];

// ---------------- generic SGEMM: C[M,N] = A[M,K] @ W[N,K]^T + bias (+epi) ----
// EPI: 0 = bias only, 1 = bias + residual R, 2 = bias + relu
template<int EPI>
__global__ __launch_bounds__(256)
void sgemm_nt(const float* __restrict__ A, const float* __restrict__ W,
              const float* __restrict__ bias, const float* __restrict__ R,
              float* __restrict__ C, int M, int N, int K)
{
    __shared__ float As[8][128];
    __shared__ float Bs[8][128];

    const int tid = threadIdx.x;
    const int bm  = blockIdx.y * 128;
    const int bn  = blockIdx.x * 128;
    const int lr  = tid >> 1;            // 0..127
    const int lc  = (tid & 1) * 4;       // 0 or 4
    const int tx  = tid & 15;            // 0..15
    const int ty  = tid >> 4;            // 0..15

    const float* Ag = A + (size_t)(bm + lr) * K + lc;
    const float* Wg = W + (size_t)(bn + lr) * K + lc;

    float acc[8][8];
#pragma unroll
    for (int i = 0; i < 8; i++)
#pragma unroll
        for (int j = 0; j < 8; j++) acc[i][j] = 0.f;

    for (int k0 = 0; k0 < K; k0 += 8) {
        float4 a4 = *(const float4*)(Ag + k0);
        float4 b4 = *(const float4*)(Wg + k0);
        __syncthreads();
        As[lc+0][lr] = a4.x; As[lc+1][lr] = a4.y; As[lc+2][lr] = a4.z; As[lc+3][lr] = a4.w;
        Bs[lc+0][lr] = b4.x; Bs[lc+1][lr] = b4.y; Bs[lc+2][lr] = b4.z; Bs[lc+3][lr] = b4.w;
        __syncthreads();
#pragma unroll
        for (int kk = 0; kk < 8; kk++) {
            float4 a0 = *(const float4*)&As[kk][ty*8];
            float4 a1 = *(const float4*)&As[kk][ty*8+4];
            float4 b0 = *(const float4*)&Bs[kk][tx*8];
            float4 b1 = *(const float4*)&Bs[kk][tx*8+4];
            float ar[8] = {a0.x,a0.y,a0.z,a0.w,a1.x,a1.y,a1.z,a1.w};
            float br[8] = {b0.x,b0.y,b0.z,b0.w,b1.x,b1.y,b1.z,b1.w};
#pragma unroll
            for (int i = 0; i < 8; i++)
#pragma unroll
                for (int j = 0; j < 8; j++)
                    acc[i][j] = fmaf(ar[i], br[j], acc[i][j]);
        }
    }

    float bb[8];
#pragma unroll
    for (int j = 0; j < 8; j++) bb[j] = bias[bn + tx*8 + j];

#pragma unroll
    for (int i = 0; i < 8; i++) {
        const int row = bm + ty*8 + i;
#pragma unroll
        for (int j = 0; j < 8; j++) {
            const int col = bn + tx*8 + j;
            float v = acc[i][j] + bb[j];
            if (EPI == 2) v = fmaxf(v, 0.f);
            if (EPI == 1) v += R[(size_t)row * N + col];
            C[(size_t)row * N + col] = v;
        }
    }
}

// ---------------- flash attention: 64-q tile per CTA, K-tiles of 64 ----------
// reads g_q/g_k/g_v, writes g_ctx. q already NOT scaled -> scale on smem load.
__global__ __launch_bounds__(256)
void attn_kernel(const int* __restrict__ mask)
{
    extern __shared__ float sm[];
    const int ST = 68;                        // padded stride (floats), 16B-aligned rows
    float* Qs = sm;                           // 64 x ST
    float* Ks = Qs + 64*ST;
    float* Vs = Ks + 64*ST;
    float* Ps = Vs + 64*ST;
    __shared__ int mS[64];

    const int q0  = blockIdx.x * 64;
    const int h   = blockIdx.y;
    const int b   = blockIdx.z;
    const int tid = threadIdx.x;
    const int tx  = tid & 15;                 // dh / kc group
    const int ty  = tid >> 4;                 // q-row group

    const float* Qg = g_q + (size_t)(b*SS) * DDIM + h*DHH;
    const float* Kg = g_k + (size_t)(b*SS) * DDIM + h*DHH;
    const float* Vg = g_v + (size_t)(b*SS) * DDIM + h*DHH;

    // load Q tile (scaled by 1/sqrt(DH) = 0.125)
#pragma unroll
    for (int it = 0; it < 4; it++) {
        int f = tid + 256*it;                 // float4 index 0..1023
        int r = f >> 4, c4 = (f & 15) << 2;
        float4 v = *(const float4*)(Qg + (size_t)(q0 + r) * DDIM + c4);
        v.x *= 0.125f; v.y *= 0.125f; v.z *= 0.125f; v.w *= 0.125f;
        *(float4*)&Qs[r*ST + c4] = v;
    }

    float m[4], l[4], acc[4][4];
#pragma unroll
    for (int i = 0; i < 4; i++) {
        m[i] = -3e38f; l[i] = 0.f;
#pragma unroll
        for (int j = 0; j < 4; j++) acc[i][j] = 0.f;
    }

    for (int kt = 0; kt < SS/64; kt++) {
        __syncthreads();
        const int kbase = kt * 64;
#pragma unroll
        for (int it = 0; it < 4; it++) {
            int f = tid + 256*it;
            int r = f >> 4, c4 = (f & 15) << 2;
            *(float4*)&Ks[r*ST + c4] = *(const float4*)(Kg + (size_t)(kbase + r) * DDIM + c4);
            *(float4*)&Vs[r*ST + c4] = *(const float4*)(Vg + (size_t)(kbase + r) * DDIM + c4);
        }
        if (tid < 64) mS[tid] = mask[b*SS + kbase + tid];
        __syncthreads();

        // scores: 4x4 per thread over DH=64
        float sc[4][4] = {};
#pragma unroll
        for (int d0 = 0; d0 < 64; d0 += 4) {
            float4 q4[4], k4[4];
#pragma unroll
            for (int i = 0; i < 4; i++) q4[i] = *(const float4*)&Qs[(ty*4+i)*ST + d0];
#pragma unroll
            for (int j = 0; j < 4; j++) k4[j] = *(const float4*)&Ks[(tx*4+j)*ST + d0];
#pragma unroll
            for (int i = 0; i < 4; i++)
#pragma unroll
                for (int j = 0; j < 4; j++)
                    sc[i][j] = fmaf(q4[i].x, k4[j].x,
                               fmaf(q4[i].y, k4[j].y,
                               fmaf(q4[i].z, k4[j].z,
                               fmaf(q4[i].w, k4[j].w, sc[i][j]))));
        }
#pragma unroll
        for (int j = 0; j < 4; j++) {
            if (mS[tx*4+j] == 0) {
#pragma unroll
                for (int i = 0; i < 4; i++) sc[i][j] = NEGV;
            }
        }

        // online softmax per q-row (row stats reduced over the 16 tx lanes)
#pragma unroll
        for (int i = 0; i < 4; i++) {
            float mt = fmaxf(fmaxf(sc[i][0], sc[i][1]), fmaxf(sc[i][2], sc[i][3]));
#pragma unroll
            for (int o = 1; o < 16; o <<= 1)
                mt = fmaxf(mt, __shfl_xor_sync(0xffffffffu, mt, o));
            float mn  = fmaxf(m[i], mt);
            float fac = __expf(m[i] - mn);
            m[i] = mn;
            float p0 = __expf(sc[i][0] - mn);
            float p1 = __expf(sc[i][1] - mn);
            float p2 = __expf(sc[i][2] - mn);
            float p3 = __expf(sc[i][3] - mn);
            float rs = p0 + p1 + p2 + p3;
#pragma unroll
            for (int o = 1; o < 16; o <<= 1)
                rs += __shfl_xor_sync(0xffffffffu, rs, o);
            l[i] = l[i] * fac + rs;
#pragma unroll
            for (int j = 0; j < 4; j++) acc[i][j] *= fac;
            *(float4*)&Ps[(ty*4+i)*ST + tx*4] = make_float4(p0, p1, p2, p3);
        }
        __syncthreads();

        // acc += P @ V  (4x4 per thread over 64 k)
#pragma unroll
        for (int k0 = 0; k0 < 64; k0 += 4) {
            float4 pv[4];
#pragma unroll
            for (int i = 0; i < 4; i++) pv[i] = *(const float4*)&Ps[(ty*4+i)*ST + k0];
            float4 v0 = *(const float4*)&Vs[(k0+0)*ST + tx*4];
            float4 v1 = *(const float4*)&Vs[(k0+1)*ST + tx*4];
            float4 v2 = *(const float4*)&Vs[(k0+2)*ST + tx*4];
            float4 v3 = *(const float4*)&Vs[(k0+3)*ST + tx*4];
#pragma unroll
            for (int i = 0; i < 4; i++) {
                acc[i][0] = fmaf(pv[i].x, v0.x, fmaf(pv[i].y, v1.x, fmaf(pv[i].z, v2.x, fmaf(pv[i].w, v3.x, acc[i][0]))));
                acc[i][1] = fmaf(pv[i].x, v0.y, fmaf(pv[i].y, v1.y, fmaf(pv[i].z, v2.y, fmaf(pv[i].w, v3.y, acc[i][1]))));
                acc[i][2] = fmaf(pv[i].x, v0.z, fmaf(pv[i].y, v1.z, fmaf(pv[i].z, v2.z, fmaf(pv[i].w, v3.z, acc[i][2]))));
                acc[i][3] = fmaf(pv[i].x, v0.w, fmaf(pv[i].y, v1.w, fmaf(pv[i].z, v2.w, fmaf(pv[i].w, v3.w, acc[i][3]))));
            }
        }
    }

    float* Og = g_ctx + (size_t)(b*SS) * DDIM + h*DHH;
#pragma unroll
    for (int i = 0; i < 4; i++) {
        float inv = 1.f / l[i];
#pragma unroll
        for (int j = 0; j < 4; j++)
            Og[(size_t)(q0 + ty*4 + i) * DDIM + tx*4 + j] = acc[i][j] * inv;
    }
}

// ---------------- LayerNorm over D=1024, one CTA per row --------------------
__global__ __launch_bounds__(256)
void ln_kernel(const float* __restrict__ y, const float* __restrict__ g,
               const float* __restrict__ bta, const int* __restrict__ mask,
               float* __restrict__ out)
{
    const int row = blockIdx.x;
    const int tid = threadIdx.x;
    const float* yr = y + (size_t)row * DDIM;
    __shared__ float red[8];

    float4 xv = *(const float4*)(yr + tid*4);
    float s = xv.x + xv.y + xv.z + xv.w;
#pragma unroll
    for (int o = 16; o > 0; o >>= 1) s += __shfl_xor_sync(0xffffffffu, s, o);
    if ((tid & 31) == 0) red[tid >> 5] = s;
    __syncthreads();
    s = 0.f;
#pragma unroll
    for (int w = 0; w < 8; w++) s += red[w];
    const float mean = s * (1.f / DDIM);

    float dx0 = xv.x - mean, dx1 = xv.y - mean, dx2 = xv.z - mean, dx3 = xv.w - mean;
    float s2 = dx0*dx0 + dx1*dx1 + dx2*dx2 + dx3*dx3;
    __syncthreads();   // red reuse
#pragma unroll
    for (int o = 16; o > 0; o >>= 1) s2 += __shfl_xor_sync(0xffffffffu, s2, o);
    if ((tid & 31) == 0) red[tid >> 5] = s2;
    __syncthreads();
    s2 = 0.f;
#pragma unroll
    for (int w = 0; w < 8; w++) s2 += red[w];
    const float rstd = rsqrtf(s2 * (1.f / DDIM) + 1e-5f);

    const float mv = mask ? (float)mask[row] : 1.f;
    float4 gv = *(const float4*)(g   + tid*4);
    float4 bv = *(const float4*)(bta + tid*4);
    float4 ov;
    ov.x = (dx0 * rstd * gv.x + bv.x) * mv;
    ov.y = (dx1 * rstd * gv.y + bv.y) * mv;
    ov.z = (dx2 * rstd * gv.z + bv.z) * mv;
    ov.w = (dx3 * rstd * gv.w + bv.w) * mv;
    *(float4*)(out + (size_t)row * DDIM + tid*4) = ov;
}

// ---------------- launch --------------------------------------------------
extern "C" void kernel_launch(void* const* d_in, const int* in_sizes, int n_in,
                              void* d_out, int out_size)
{
    const float* x    = (const float*)d_in[0];
    const int*   mask = (const int*)  d_in[1];
    const float* wq = (const float*)d_in[2];  const float* bq = (const float*)d_in[3];
    const float* wk = (const float*)d_in[4];  const float* bk = (const float*)d_in[5];
    const float* wv = (const float*)d_in[6];  const float* bv = (const float*)d_in[7];
    const float* wo = (const float*)d_in[8];  const float* bo = (const float*)d_in[9];
    const float* l1g = (const float*)d_in[10]; const float* l1b = (const float*)d_in[11];
    const float* w1 = (const float*)d_in[12]; const float* b1 = (const float*)d_in[13];
    const float* w2 = (const float*)d_in[14]; const float* b2 = (const float*)d_in[15];
    const float* l2g = (const float*)d_in[16]; const float* l2b = (const float*)d_in[17];

    float *q, *k, *v, *ctx, *y1, *t, *hb, *y2;
    cudaGetSymbolAddress((void**)&q,   g_q);
    cudaGetSymbolAddress((void**)&k,   g_k);
    cudaGetSymbolAddress((void**)&v,   g_v);
    cudaGetSymbolAddress((void**)&ctx, g_ctx);
    cudaGetSymbolAddress((void**)&y1,  g_y1);
    cudaGetSymbolAddress((void**)&t,   g_t);
    cudaGetSymbolAddress((void**)&hb,  g_h);
    cudaGetSymbolAddress((void**)&y2,  g_y2);

    const int ATTN_SMEM = 64 * 68 * 4 * sizeof(float);   // 69632 B
    cudaFuncSetAttribute(attn_kernel, cudaFuncAttributeMaxDynamicSharedMemorySize, ATTN_SMEM);

    dim3 gD(DDIM/128, MM/128);   // N=1024 tiles x M=4096 tiles
    dim3 gF(FF/128,   MM/128);   // N=4096 tiles

    sgemm_nt<0><<<gD, 256>>>(x,   wq, bq, nullptr, q,  MM, DDIM, DDIM);
    sgemm_nt<0><<<gD, 256>>>(x,   wk, bk, nullptr, k,  MM, DDIM, DDIM);
    sgemm_nt<0><<<gD, 256>>>(x,   wv, bv, nullptr, v,  MM, DDIM, DDIM);

    attn_kernel<<<dim3(SS/64, HH, BB), 256, ATTN_SMEM>>>(mask);

    sgemm_nt<1><<<gD, 256>>>(ctx, wo, bo, x,       y1, MM, DDIM, DDIM);
    ln_kernel<<<MM, 256>>>(y1, l1g, l1b, nullptr, t);

    sgemm_nt<2><<<gF, 256>>>(t,   w1, b1, nullptr, hb, MM, FF,   DDIM);
    sgemm_nt<1><<<gD, 256>>>(hb,  w2, b2, t,       y2, MM, DDIM, FF);
    ln_kernel<<<MM, 256>>>(y2, l2g, l2b, mask, (float*)d_out);
}

// round 4
// speedup vs baseline: 1.9869x; 1.9869x over previous
#include <cuda_runtime.h>
#include <math.h>
#include <stdint.h>

#define BB   4
#define SS   1024
#define DDIM 1024
#define HH   16
#define DHH  64
#define FF   4096
#define MM   (BB*SS)      // 4096 rows
#define NEGV (-1e20f)

// ---------------- scratch (allocation-free: device globals) ----------------
__device__ float g_q  [MM*DDIM];
__device__ float g_k  [MM*DDIM];
__device__ float g_v  [MM*DDIM];
__device__ float g_ctx[MM*DDIM];
__device__ float g_y1 [MM*DDIM];
__device__ float g_t  [MM*DDIM];
__device__ float g_h  [(size_t)MM*FF];
__device__ float g_y2 [MM*DDIM];

// ---------------- helpers ---------------------------------------------------
__device__ __forceinline__ float to_tf32(float x) {
    float y;
    asm("cvt.rna.tf32.f32 %0, %1;" : "=f"(y) : "f"(x));
    return y;
}

#define MMA_TF32(d, a, b)                                                      \
    asm volatile("mma.sync.aligned.m16n8k8.row.col.f32.tf32.tf32.f32 "         \
                 "{%0,%1,%2,%3}, {%4,%5,%6,%7}, {%8,%9}, {%0,%1,%2,%3};"       \
                 : "+f"((d)[0]), "+f"((d)[1]), "+f"((d)[2]), "+f"((d)[3])      \
                 : "r"((a)[0]), "r"((a)[1]), "r"((a)[2]), "r"((a)[3]),         \
                   "r"((b)[0]), "r"((b)[1]))

// ---------------- tf32 mma.sync GEMM: C[M,N] = A[M,K] @ W[N,K]^T + bias -----
// tile 128x128, BK=16, 8 warps (4M x 2N), warp tile 32x64, double-buffered.
// EPI: 0 = bias, 1 = bias + residual R, 2 = bias + relu
#define SST 20   // smem row stride in floats (conflict-free fragment loads)

template<int EPI>
__global__ __launch_bounds__(256, 2)
void mgemm(const float* __restrict__ A, const float* __restrict__ W,
           const float* __restrict__ bias, const float* __restrict__ R,
           float* __restrict__ C, int M, int N, int K)
{
    __shared__ __align__(16) float As[2][128][SST];
    __shared__ __align__(16) float Bs[2][128][SST];

    const int tid  = threadIdx.x;
    const int lane = tid & 31;
    const int wid  = tid >> 5;
    const int wm   = wid >> 1;        // 0..3 -> warp M offset *32
    const int wn   = wid & 1;         // 0..1 -> warp N offset *64
    const int g    = lane >> 2;       // 0..7
    const int tc   = lane & 3;        // 0..3
    const int bm   = blockIdx.y * 128;
    const int bn   = blockIdx.x * 128;

    // staging coords: 512 float4 per tile (128 rows x 16 cols)
    const int f0 = tid,        r0s = f0 >> 2, c0s = (f0 & 3) << 2;
    const int f1 = tid + 256,  r1s = f1 >> 2, c1s = (f1 & 3) << 2;

    const float* Ag0 = A + (size_t)(bm + r0s) * K + c0s;
    const float* Ag1 = A + (size_t)(bm + r1s) * K + c1s;
    const float* Wg0 = W + (size_t)(bn + r0s) * K + c0s;
    const float* Wg1 = W + (size_t)(bn + r1s) * K + c1s;

    float acc[2][8][4];
#pragma unroll
    for (int i = 0; i < 2; i++)
#pragma unroll
        for (int j = 0; j < 8; j++)
#pragma unroll
            for (int e = 0; e < 4; e++) acc[i][j][e] = 0.f;

    // prologue: stage chunk 0 into buffer 0
    {
        float4 a0 = *(const float4*)(Ag0);
        float4 a1 = *(const float4*)(Ag1);
        float4 b0 = *(const float4*)(Wg0);
        float4 b1 = *(const float4*)(Wg1);
        As[0][r0s][c0s+0] = to_tf32(a0.x); As[0][r0s][c0s+1] = to_tf32(a0.y);
        As[0][r0s][c0s+2] = to_tf32(a0.z); As[0][r0s][c0s+3] = to_tf32(a0.w);
        As[0][r1s][c1s+0] = to_tf32(a1.x); As[0][r1s][c1s+1] = to_tf32(a1.y);
        As[0][r1s][c1s+2] = to_tf32(a1.z); As[0][r1s][c1s+3] = to_tf32(a1.w);
        Bs[0][r0s][c0s+0] = to_tf32(b0.x); Bs[0][r0s][c0s+1] = to_tf32(b0.y);
        Bs[0][r0s][c0s+2] = to_tf32(b0.z); Bs[0][r0s][c0s+3] = to_tf32(b0.w);
        Bs[0][r1s][c1s+0] = to_tf32(b1.x); Bs[0][r1s][c1s+1] = to_tf32(b1.y);
        Bs[0][r1s][c1s+2] = to_tf32(b1.z); Bs[0][r1s][c1s+3] = to_tf32(b1.w);
    }
    __syncthreads();

    const int nch = K >> 4;
    for (int ch = 0; ch < nch; ch++) {
        const int buf = ch & 1;
        float4 pa0, pa1, pb0, pb1;
        const bool more = (ch + 1) < nch;
        if (more) {
            const int k0 = (ch + 1) << 4;
            pa0 = *(const float4*)(Ag0 + k0);
            pa1 = *(const float4*)(Ag1 + k0);
            pb0 = *(const float4*)(Wg0 + k0);
            pb1 = *(const float4*)(Wg1 + k0);
        }

#pragma unroll
        for (int kk = 0; kk < 2; kk++) {
            const int k8 = kk * 8;
            uint32_t af[2][4], bf[8][2];
#pragma unroll
            for (int fi = 0; fi < 2; fi++) {
                const float* ap = &As[buf][wm*32 + fi*16 + g][k8 + tc];
                af[fi][0] = __float_as_uint(ap[0]);
                af[fi][1] = __float_as_uint(ap[8*SST]);
                af[fi][2] = __float_as_uint(ap[4]);
                af[fi][3] = __float_as_uint(ap[8*SST + 4]);
            }
#pragma unroll
            for (int fj = 0; fj < 8; fj++) {
                const float* bp = &Bs[buf][wn*64 + fj*8 + g][k8 + tc];
                bf[fj][0] = __float_as_uint(bp[0]);
                bf[fj][1] = __float_as_uint(bp[4]);
            }
#pragma unroll
            for (int fi = 0; fi < 2; fi++)
#pragma unroll
                for (int fj = 0; fj < 8; fj++)
                    MMA_TF32(acc[fi][fj], af[fi], bf[fj]);
        }

        if (more) {
            const int nb = buf ^ 1;
            As[nb][r0s][c0s+0] = to_tf32(pa0.x); As[nb][r0s][c0s+1] = to_tf32(pa0.y);
            As[nb][r0s][c0s+2] = to_tf32(pa0.z); As[nb][r0s][c0s+3] = to_tf32(pa0.w);
            As[nb][r1s][c1s+0] = to_tf32(pa1.x); As[nb][r1s][c1s+1] = to_tf32(pa1.y);
            As[nb][r1s][c1s+2] = to_tf32(pa1.z); As[nb][r1s][c1s+3] = to_tf32(pa1.w);
            Bs[nb][r0s][c0s+0] = to_tf32(pb0.x); Bs[nb][r0s][c0s+1] = to_tf32(pb0.y);
            Bs[nb][r0s][c0s+2] = to_tf32(pb0.z); Bs[nb][r0s][c0s+3] = to_tf32(pb0.w);
            Bs[nb][r1s][c1s+0] = to_tf32(pb1.x); Bs[nb][r1s][c1s+1] = to_tf32(pb1.y);
            Bs[nb][r1s][c1s+2] = to_tf32(pb1.z); Bs[nb][r1s][c1s+3] = to_tf32(pb1.w);
            __syncthreads();
        }
    }

    // epilogue: d0,d1 -> (row=g, col=2tc,2tc+1); d2,d3 -> (row=g+8, same)
#pragma unroll
    for (int fi = 0; fi < 2; fi++) {
        const int ra = bm + wm*32 + fi*16 + g;
#pragma unroll
        for (int fj = 0; fj < 8; fj++) {
            const int c = bn + wn*64 + fj*8 + 2*tc;
            const float2 b2 = *(const float2*)(bias + c);
            float x0 = acc[fi][fj][0] + b2.x;
            float x1 = acc[fi][fj][1] + b2.y;
            float x2 = acc[fi][fj][2] + b2.x;
            float x3 = acc[fi][fj][3] + b2.y;
            if (EPI == 2) {
                x0 = fmaxf(x0, 0.f); x1 = fmaxf(x1, 0.f);
                x2 = fmaxf(x2, 0.f); x3 = fmaxf(x3, 0.f);
            }
            if (EPI == 1) {
                const float2 r2a = *(const float2*)(R + (size_t)ra * N + c);
                const float2 r2b = *(const float2*)(R + (size_t)(ra+8) * N + c);
                x0 += r2a.x; x1 += r2a.y; x2 += r2b.x; x3 += r2b.y;
            }
            float2 o0 = make_float2(x0, x1);
            float2 o1 = make_float2(x2, x3);
            *(float2*)(C + (size_t)ra * N + c)     = o0;
            *(float2*)(C + (size_t)(ra+8) * N + c) = o1;
        }
    }
}

// ---------------- flash attention: 64-q tile per CTA, K-tiles of 64 ----------
__global__ __launch_bounds__(256)
void attn_kernel(const int* __restrict__ mask)
{
    extern __shared__ float smf[];
    const int ST = 68;
    float* Qs = smf;
    float* Ks = Qs + 64*ST;
    float* Vs = Ks + 64*ST;
    float* Ps = Vs + 64*ST;
    __shared__ int mS[64];

    const int q0  = blockIdx.x * 64;
    const int h   = blockIdx.y;
    const int b   = blockIdx.z;
    const int tid = threadIdx.x;
    const int tx  = tid & 15;
    const int ty  = tid >> 4;

    const float* Qg = g_q + (size_t)(b*SS) * DDIM + h*DHH;
    const float* Kg = g_k + (size_t)(b*SS) * DDIM + h*DHH;
    const float* Vg = g_v + (size_t)(b*SS) * DDIM + h*DHH;

#pragma unroll
    for (int it = 0; it < 4; it++) {
        int f = tid + 256*it;
        int r = f >> 4, c4 = (f & 15) << 2;
        float4 v = *(const float4*)(Qg + (size_t)(q0 + r) * DDIM + c4);
        v.x *= 0.125f; v.y *= 0.125f; v.z *= 0.125f; v.w *= 0.125f;
        *(float4*)&Qs[r*ST + c4] = v;
    }

    float m[4], l[4], acc[4][4];
#pragma unroll
    for (int i = 0; i < 4; i++) {
        m[i] = -3e38f; l[i] = 0.f;
#pragma unroll
        for (int j = 0; j < 4; j++) acc[i][j] = 0.f;
    }

    for (int kt = 0; kt < SS/64; kt++) {
        __syncthreads();
        const int kbase = kt * 64;
#pragma unroll
        for (int it = 0; it < 4; it++) {
            int f = tid + 256*it;
            int r = f >> 4, c4 = (f & 15) << 2;
            *(float4*)&Ks[r*ST + c4] = *(const float4*)(Kg + (size_t)(kbase + r) * DDIM + c4);
            *(float4*)&Vs[r*ST + c4] = *(const float4*)(Vg + (size_t)(kbase + r) * DDIM + c4);
        }
        if (tid < 64) mS[tid] = mask[b*SS + kbase + tid];
        __syncthreads();

        float sc[4][4] = {};
#pragma unroll
        for (int d0 = 0; d0 < 64; d0 += 4) {
            float4 q4[4], k4[4];
#pragma unroll
            for (int i = 0; i < 4; i++) q4[i] = *(const float4*)&Qs[(ty*4+i)*ST + d0];
#pragma unroll
            for (int j = 0; j < 4; j++) k4[j] = *(const float4*)&Ks[(tx*4+j)*ST + d0];
#pragma unroll
            for (int i = 0; i < 4; i++)
#pragma unroll
                for (int j = 0; j < 4; j++)
                    sc[i][j] = fmaf(q4[i].x, k4[j].x,
                               fmaf(q4[i].y, k4[j].y,
                               fmaf(q4[i].z, k4[j].z,
                               fmaf(q4[i].w, k4[j].w, sc[i][j]))));
        }
#pragma unroll
        for (int j = 0; j < 4; j++) {
            if (mS[tx*4+j] == 0) {
#pragma unroll
                for (int i = 0; i < 4; i++) sc[i][j] = NEGV;
            }
        }

#pragma unroll
        for (int i = 0; i < 4; i++) {
            float mt = fmaxf(fmaxf(sc[i][0], sc[i][1]), fmaxf(sc[i][2], sc[i][3]));
#pragma unroll
            for (int o = 1; o < 16; o <<= 1)
                mt = fmaxf(mt, __shfl_xor_sync(0xffffffffu, mt, o));
            float mn  = fmaxf(m[i], mt);
            float fac = __expf(m[i] - mn);
            m[i] = mn;
            float p0 = __expf(sc[i][0] - mn);
            float p1 = __expf(sc[i][1] - mn);
            float p2 = __expf(sc[i][2] - mn);
            float p3 = __expf(sc[i][3] - mn);
            float rs = p0 + p1 + p2 + p3;
#pragma unroll
            for (int o = 1; o < 16; o <<= 1)
                rs += __shfl_xor_sync(0xffffffffu, rs, o);
            l[i] = l[i] * fac + rs;
#pragma unroll
            for (int j = 0; j < 4; j++) acc[i][j] *= fac;
            *(float4*)&Ps[(ty*4+i)*ST + tx*4] = make_float4(p0, p1, p2, p3);
        }
        __syncthreads();

#pragma unroll
        for (int k0 = 0; k0 < 64; k0 += 4) {
            float4 pv[4];
#pragma unroll
            for (int i = 0; i < 4; i++) pv[i] = *(const float4*)&Ps[(ty*4+i)*ST + k0];
            float4 v0 = *(const float4*)&Vs[(k0+0)*ST + tx*4];
            float4 v1 = *(const float4*)&Vs[(k0+1)*ST + tx*4];
            float4 v2 = *(const float4*)&Vs[(k0+2)*ST + tx*4];
            float4 v3 = *(const float4*)&Vs[(k0+3)*ST + tx*4];
#pragma unroll
            for (int i = 0; i < 4; i++) {
                acc[i][0] = fmaf(pv[i].x, v0.x, fmaf(pv[i].y, v1.x, fmaf(pv[i].z, v2.x, fmaf(pv[i].w, v3.x, acc[i][0]))));
                acc[i][1] = fmaf(pv[i].x, v0.y, fmaf(pv[i].y, v1.y, fmaf(pv[i].z, v2.y, fmaf(pv[i].w, v3.y, acc[i][1]))));
                acc[i][2] = fmaf(pv[i].x, v0.z, fmaf(pv[i].y, v1.z, fmaf(pv[i].z, v2.z, fmaf(pv[i].w, v3.z, acc[i][2]))));
                acc[i][3] = fmaf(pv[i].x, v0.w, fmaf(pv[i].y, v1.w, fmaf(pv[i].z, v2.w, fmaf(pv[i].w, v3.w, acc[i][3]))));
            }
        }
    }

    float* Og = g_ctx + (size_t)(b*SS) * DDIM + h*DHH;
#pragma unroll
    for (int i = 0; i < 4; i++) {
        float inv = 1.f / l[i];
#pragma unroll
        for (int j = 0; j < 4; j++)
            Og[(size_t)(q0 + ty*4 + i) * DDIM + tx*4 + j] = acc[i][j] * inv;
    }
}

// ---------------- LayerNorm over D=1024, one CTA per row --------------------
__global__ __launch_bounds__(256)
void ln_kernel(const float* __restrict__ y, const float* __restrict__ g,
               const float* __restrict__ bta, const int* __restrict__ mask,
               float* __restrict__ out)
{
    const int row = blockIdx.x;
    const int tid = threadIdx.x;
    const float* yr = y + (size_t)row * DDIM;
    __shared__ float red[8];

    float4 xv = *(const float4*)(yr + tid*4);
    float s = xv.x + xv.y + xv.z + xv.w;
#pragma unroll
    for (int o = 16; o > 0; o >>= 1) s += __shfl_xor_sync(0xffffffffu, s, o);
    if ((tid & 31) == 0) red[tid >> 5] = s;
    __syncthreads();
    s = 0.f;
#pragma unroll
    for (int w = 0; w < 8; w++) s += red[w];
    const float mean = s * (1.f / DDIM);

    float dx0 = xv.x - mean, dx1 = xv.y - mean, dx2 = xv.z - mean, dx3 = xv.w - mean;
    float s2 = dx0*dx0 + dx1*dx1 + dx2*dx2 + dx3*dx3;
    __syncthreads();
#pragma unroll
    for (int o = 16; o > 0; o >>= 1) s2 += __shfl_xor_sync(0xffffffffu, s2, o);
    if ((tid & 31) == 0) red[tid >> 5] = s2;
    __syncthreads();
    s2 = 0.f;
#pragma unroll
    for (int w = 0; w < 8; w++) s2 += red[w];
    const float rstd = rsqrtf(s2 * (1.f / DDIM) + 1e-5f);

    const float mv = mask ? (float)mask[row] : 1.f;
    float4 gv = *(const float4*)(g   + tid*4);
    float4 bv = *(const float4*)(bta + tid*4);
    float4 ov;
    ov.x = (dx0 * rstd * gv.x + bv.x) * mv;
    ov.y = (dx1 * rstd * gv.y + bv.y) * mv;
    ov.z = (dx2 * rstd * gv.z + bv.z) * mv;
    ov.w = (dx3 * rstd * gv.w + bv.w) * mv;
    *(float4*)(out + (size_t)row * DDIM + tid*4) = ov;
}

// ---------------- launch --------------------------------------------------
extern "C" void kernel_launch(void* const* d_in, const int* in_sizes, int n_in,
                              void* d_out, int out_size)
{
    const float* x    = (const float*)d_in[0];
    const int*   mask = (const int*)  d_in[1];
    const float* wq = (const float*)d_in[2];  const float* bq = (const float*)d_in[3];
    const float* wk = (const float*)d_in[4];  const float* bk = (const float*)d_in[5];
    const float* wv = (const float*)d_in[6];  const float* bv = (const float*)d_in[7];
    const float* wo = (const float*)d_in[8];  const float* bo = (const float*)d_in[9];
    const float* l1g = (const float*)d_in[10]; const float* l1b = (const float*)d_in[11];
    const float* w1 = (const float*)d_in[12]; const float* b1 = (const float*)d_in[13];
    const float* w2 = (const float*)d_in[14]; const float* b2 = (const float*)d_in[15];
    const float* l2g = (const float*)d_in[16]; const float* l2b = (const float*)d_in[17];

    float *q, *k, *v, *ctx, *y1, *t, *hb, *y2;
    cudaGetSymbolAddress((void**)&q,   g_q);
    cudaGetSymbolAddress((void**)&k,   g_k);
    cudaGetSymbolAddress((void**)&v,   g_v);
    cudaGetSymbolAddress((void**)&ctx, g_ctx);
    cudaGetSymbolAddress((void**)&y1,  g_y1);
    cudaGetSymbolAddress((void**)&t,   g_t);
    cudaGetSymbolAddress((void**)&hb,  g_h);
    cudaGetSymbolAddress((void**)&y2,  g_y2);

    const int ATTN_SMEM = 64 * 68 * 4 * sizeof(float);
    cudaFuncSetAttribute(attn_kernel, cudaFuncAttributeMaxDynamicSharedMemorySize, ATTN_SMEM);

    dim3 gD(DDIM/128, MM/128);   // 8 x 32
    dim3 gF(FF/128,   MM/128);   // 32 x 32

    mgemm<0><<<gD, 256>>>(x,   wq, bq, nullptr, q,  MM, DDIM, DDIM);
    mgemm<0><<<gD, 256>>>(x,   wk, bk, nullptr, k,  MM, DDIM, DDIM);
    mgemm<0><<<gD, 256>>>(x,   wv, bv, nullptr, v,  MM, DDIM, DDIM);

    attn_kernel<<<dim3(SS/64, HH, BB), 256, ATTN_SMEM>>>(mask);

    mgemm<1><<<gD, 256>>>(ctx, wo, bo, x,       y1, MM, DDIM, DDIM);
    ln_kernel<<<MM, 256>>>(y1, l1g, l1b, nullptr, t);

    mgemm<2><<<gF, 256>>>(t,   w1, b1, nullptr, hb, MM, FF,   DDIM);
    mgemm<1><<<gD, 256>>>(hb,  w2, b2, t,       y2, MM, DDIM, FF);
    ln_kernel<<<MM, 256>>>(y2, l2g, l2b, mask, (float*)d_out);
}

// round 12
// speedup vs baseline: 2.9466x; 1.4830x over previous
#include <cuda_runtime.h>
#include <math.h>
#include <stdint.h>

#define BB   4
#define SS   1024
#define DDIM 1024
#define HH   16
#define DHH  64
#define FF   4096
#define MM   (BB*SS)      // 4096 rows
#define NEGV (-1e20f)

// ---------------- scratch (allocation-free: device globals) ----------------
__device__ float g_q  [MM*DDIM];
__device__ float g_k  [MM*DDIM];
__device__ float g_v  [MM*DDIM];
__device__ float g_ctx[MM*DDIM];
__device__ float g_y1 [MM*DDIM];
__device__ float g_t  [MM*DDIM];
__device__ float g_h  [(size_t)MM*FF];
__device__ float g_y2 [MM*DDIM];

// ---------------- helpers ---------------------------------------------------
__device__ __forceinline__ float to_tf32(float x) {
    float y;
    asm("cvt.rna.tf32.f32 %0, %1;" : "=f"(y) : "f"(x));
    return y;
}

#define MMA_TF32(d, a, b)                                                      \
    asm volatile("mma.sync.aligned.m16n8k8.row.col.f32.tf32.tf32.f32 "         \
                 "{%0,%1,%2,%3}, {%4,%5,%6,%7}, {%8,%9}, {%0,%1,%2,%3};"       \
                 : "+f"((d)[0]), "+f"((d)[1]), "+f"((d)[2]), "+f"((d)[3])      \
                 : "r"((a)[0]), "r"((a)[1]), "r"((a)[2]), "r"((a)[3]),         \
                   "r"((b)[0]), "r"((b)[1]))

#define SST 20   // smem row stride in floats (conflict-free fragment loads)

// Shared GEMM body: C[M,N] = A[M,K] @ W[N,K]^T + bias (+epi).
// Caller provides the double-buffered smem tiles.
template<int EPI>
__device__ __forceinline__ void mgemm_body(
    const float* __restrict__ A, const float* __restrict__ W,
    const float* __restrict__ bias, const float* __restrict__ R,
    float* __restrict__ C, int M, int N, int K,
    float (&As)[2][128][SST], float (&Bs)[2][128][SST],
    int bm, int bn)
{
    const int tid  = threadIdx.x;
    const int lane = tid & 31;
    const int wid  = tid >> 5;
    const int wm   = wid >> 1;        // 0..3 -> warp M offset *32
    const int wn   = wid & 1;         // 0..1 -> warp N offset *64
    const int g    = lane >> 2;       // 0..7
    const int tc   = lane & 3;        // 0..3

    // staging coords: 512 float4 per tile (128 rows x 16 cols)
    const int f0 = tid,        r0s = f0 >> 2, c0s = (f0 & 3) << 2;
    const int f1 = tid + 256,  r1s = f1 >> 2, c1s = (f1 & 3) << 2;

    const float* Ag0 = A + (size_t)(bm + r0s) * K + c0s;
    const float* Ag1 = A + (size_t)(bm + r1s) * K + c1s;
    const float* Wg0 = W + (size_t)(bn + r0s) * K + c0s;
    const float* Wg1 = W + (size_t)(bn + r1s) * K + c1s;

    float acc[2][8][4];
#pragma unroll
    for (int i = 0; i < 2; i++)
#pragma unroll
        for (int j = 0; j < 8; j++)
#pragma unroll
            for (int e = 0; e < 4; e++) acc[i][j][e] = 0.f;

    // prologue: stage chunk 0 into buffer 0
    {
        float4 a0 = *(const float4*)(Ag0);
        float4 a1 = *(const float4*)(Ag1);
        float4 b0 = *(const float4*)(Wg0);
        float4 b1 = *(const float4*)(Wg1);
        As[0][r0s][c0s+0] = to_tf32(a0.x); As[0][r0s][c0s+1] = to_tf32(a0.y);
        As[0][r0s][c0s+2] = to_tf32(a0.z); As[0][r0s][c0s+3] = to_tf32(a0.w);
        As[0][r1s][c1s+0] = to_tf32(a1.x); As[0][r1s][c1s+1] = to_tf32(a1.y);
        As[0][r1s][c1s+2] = to_tf32(a1.z); As[0][r1s][c1s+3] = to_tf32(a1.w);
        Bs[0][r0s][c0s+0] = to_tf32(b0.x); Bs[0][r0s][c0s+1] = to_tf32(b0.y);
        Bs[0][r0s][c0s+2] = to_tf32(b0.z); Bs[0][r0s][c0s+3] = to_tf32(b0.w);
        Bs[0][r1s][c1s+0] = to_tf32(b1.x); Bs[0][r1s][c1s+1] = to_tf32(b1.y);
        Bs[0][r1s][c1s+2] = to_tf32(b1.z); Bs[0][r1s][c1s+3] = to_tf32(b1.w);
    }
    __syncthreads();

    const int nch = K >> 4;
    for (int ch = 0; ch < nch; ch++) {
        const int buf = ch & 1;
        float4 pa0, pa1, pb0, pb1;
        const bool more = (ch + 1) < nch;
        if (more) {
            const int k0 = (ch + 1) << 4;
            pa0 = *(const float4*)(Ag0 + k0);
            pa1 = *(const float4*)(Ag1 + k0);
            pb0 = *(const float4*)(Wg0 + k0);
            pb1 = *(const float4*)(Wg1 + k0);
        }

#pragma unroll
        for (int kk = 0; kk < 2; kk++) {
            const int k8 = kk * 8;
            uint32_t af[2][4], bf[8][2];
#pragma unroll
            for (int fi = 0; fi < 2; fi++) {
                const float* ap = &As[buf][wm*32 + fi*16 + g][k8 + tc];
                af[fi][0] = __float_as_uint(ap[0]);
                af[fi][1] = __float_as_uint(ap[8*SST]);
                af[fi][2] = __float_as_uint(ap[4]);
                af[fi][3] = __float_as_uint(ap[8*SST + 4]);
            }
#pragma unroll
            for (int fj = 0; fj < 8; fj++) {
                const float* bp = &Bs[buf][wn*64 + fj*8 + g][k8 + tc];
                bf[fj][0] = __float_as_uint(bp[0]);
                bf[fj][1] = __float_as_uint(bp[4]);
            }
#pragma unroll
            for (int fi = 0; fi < 2; fi++)
#pragma unroll
                for (int fj = 0; fj < 8; fj++)
                    MMA_TF32(acc[fi][fj], af[fi], bf[fj]);
        }

        if (more) {
            const int nb = buf ^ 1;
            As[nb][r0s][c0s+0] = to_tf32(pa0.x); As[nb][r0s][c0s+1] = to_tf32(pa0.y);
            As[nb][r0s][c0s+2] = to_tf32(pa0.z); As[nb][r0s][c0s+3] = to_tf32(pa0.w);
            As[nb][r1s][c1s+0] = to_tf32(pa1.x); As[nb][r1s][c1s+1] = to_tf32(pa1.y);
            As[nb][r1s][c1s+2] = to_tf32(pa1.z); As[nb][r1s][c1s+3] = to_tf32(pa1.w);
            Bs[nb][r0s][c0s+0] = to_tf32(pb0.x); Bs[nb][r0s][c0s+1] = to_tf32(pb0.y);
            Bs[nb][r0s][c0s+2] = to_tf32(pb0.z); Bs[nb][r0s][c0s+3] = to_tf32(pb0.w);
            Bs[nb][r1s][c1s+0] = to_tf32(pb1.x); Bs[nb][r1s][c1s+1] = to_tf32(pb1.y);
            Bs[nb][r1s][c1s+2] = to_tf32(pb1.z); Bs[nb][r1s][c1s+3] = to_tf32(pb1.w);
            __syncthreads();
        }
    }

    // epilogue: d0,d1 -> (row=g, col=2tc,2tc+1); d2,d3 -> (row=g+8, same)
#pragma unroll
    for (int fi = 0; fi < 2; fi++) {
        const int ra = bm + wm*32 + fi*16 + g;
#pragma unroll
        for (int fj = 0; fj < 8; fj++) {
            const int c = bn + wn*64 + fj*8 + 2*tc;
            const float2 b2 = *(const float2*)(bias + c);
            float x0 = acc[fi][fj][0] + b2.x;
            float x1 = acc[fi][fj][1] + b2.y;
            float x2 = acc[fi][fj][2] + b2.x;
            float x3 = acc[fi][fj][3] + b2.y;
            if (EPI == 2) {
                x0 = fmaxf(x0, 0.f); x1 = fmaxf(x1, 0.f);
                x2 = fmaxf(x2, 0.f); x3 = fmaxf(x3, 0.f);
            }
            if (EPI == 1) {
                const float2 r2a = *(const float2*)(R + (size_t)ra * N + c);
                const float2 r2b = *(const float2*)(R + (size_t)(ra+8) * N + c);
                x0 += r2a.x; x1 += r2a.y; x2 += r2b.x; x3 += r2b.y;
            }
            float2 o0 = make_float2(x0, x1);
            float2 o1 = make_float2(x2, x3);
            *(float2*)(C + (size_t)ra * N + c)     = o0;
            *(float2*)(C + (size_t)(ra+8) * N + c) = o1;
        }
    }
}

template<int EPI>
__global__ __launch_bounds__(256, 2)
void mgemm(const float* __restrict__ A, const float* __restrict__ W,
           const float* __restrict__ bias, const float* __restrict__ R,
           float* __restrict__ C, int M, int N, int K)
{
    __shared__ __align__(16) float As[2][128][SST];
    __shared__ __align__(16) float Bs[2][128][SST];
    mgemm_body<EPI>(A, W, bias, R, C, M, N, K, As, Bs,
                    blockIdx.y * 128, blockIdx.x * 128);
}

// fused QKV: blockIdx.z selects (W, bias, C); one launch = 3x the CTAs.
__global__ __launch_bounds__(256, 2)
void qkv_gemm(const float* __restrict__ A,
              const float* __restrict__ wq, const float* __restrict__ bq,
              const float* __restrict__ wk, const float* __restrict__ bk,
              const float* __restrict__ wv, const float* __restrict__ bv,
              float* __restrict__ q, float* __restrict__ k, float* __restrict__ v)
{
    __shared__ __align__(16) float As[2][128][SST];
    __shared__ __align__(16) float Bs[2][128][SST];
    const int z = blockIdx.z;
    const float* W    = (z == 0) ? wq : (z == 1) ? wk : wv;
    const float* bias = (z == 0) ? bq : (z == 1) ? bk : bv;
    float*       C    = (z == 0) ? q  : (z == 1) ? k  : v;
    mgemm_body<0>(A, W, bias, nullptr, C, MM, DDIM, DDIM, As, Bs,
                  blockIdx.y * 128, blockIdx.x * 128);
}

// ---------------- tf32 mma flash attention ----------------------------------
// CTA: 128 threads (4 warps). Q-tile 64 (16 rows/warp), K-tile 64, DH=64.
// smem stride 68 (== 4 mod 32) -> conflict-free fragment LDS.
#define AST 68
#define ATTN_SMEM_B (3*64*AST*4 + 64*4)

__global__ __launch_bounds__(128)
void attn_mma(const int* __restrict__ mask)
{
    extern __shared__ float smf[];
    float* Ks  = smf;              // 64 x AST  (key x dh), tf32
    float* Vts = Ks  + 64*AST;     // 64 x AST  (dh x key), tf32
    float* Ps  = Vts + 64*AST;     // 64 x AST  (q x key), tf32; also Q staging
    int*   mS  = (int*)(Ps + 64*AST);

    const int q0   = blockIdx.x * 64;
    const int h    = blockIdx.y;
    const int b    = blockIdx.z;
    const int tid  = threadIdx.x;
    const int wid  = tid >> 5, lane = tid & 31;
    const int g    = lane >> 2, tc = lane & 3;
    const int w16  = wid * 16;

    const float* Qg = g_q + (size_t)(b*SS)*DDIM + h*DHH;
    const float* Kg = g_k + (size_t)(b*SS)*DDIM + h*DHH;
    const float* Vg = g_v + (size_t)(b*SS)*DDIM + h*DHH;

    // stage Q (scaled by 1/8, tf32) into Ps region, then load fragments to regs
#pragma unroll
    for (int it = 0; it < 8; it++) {
        int f = tid + 128*it;                 // 1024 float4 = 64 x 64
        int r = f >> 4, c4 = (f & 15) << 2;
        float4 v = *(const float4*)(Qg + (size_t)(q0 + r)*DDIM + c4);
        Ps[r*AST + c4 + 0] = to_tf32(v.x * 0.125f);
        Ps[r*AST + c4 + 1] = to_tf32(v.y * 0.125f);
        Ps[r*AST + c4 + 2] = to_tf32(v.z * 0.125f);
        Ps[r*AST + c4 + 3] = to_tf32(v.w * 0.125f);
    }
    __syncthreads();

    uint32_t aq[8][4];
#pragma unroll
    for (int ks = 0; ks < 8; ks++) {
        const float* ap = &Ps[(w16 + g)*AST + ks*8 + tc];
        aq[ks][0] = __float_as_uint(ap[0]);
        aq[ks][1] = __float_as_uint(ap[8*AST]);
        aq[ks][2] = __float_as_uint(ap[4]);
        aq[ks][3] = __float_as_uint(ap[8*AST + 4]);
    }

    float m0 = -3e38f, m1 = -3e38f, l0 = 0.f, l1 = 0.f;
    float acc[8][4];
#pragma unroll
    for (int fj = 0; fj < 8; fj++)
#pragma unroll
        for (int e = 0; e < 4; e++) acc[fj][e] = 0.f;

    for (int kt = 0; kt < SS/64; kt++) {
        __syncthreads();                      // protect Ks/Vts (and Ps on kt=0)
        const int kbase = kt * 64;
        // stage K (tf32) and V transposed (tf32)
#pragma unroll
        for (int it = 0; it < 8; it++) {
            int f = tid + 128*it;
            int r = f >> 4, c4 = (f & 15) << 2;
            float4 kv = *(const float4*)(Kg + (size_t)(kbase + r)*DDIM + c4);
            Ks[r*AST + c4 + 0] = to_tf32(kv.x);
            Ks[r*AST + c4 + 1] = to_tf32(kv.y);
            Ks[r*AST + c4 + 2] = to_tf32(kv.z);
            Ks[r*AST + c4 + 3] = to_tf32(kv.w);
            float4 vv = *(const float4*)(Vg + (size_t)(kbase + r)*DDIM + c4);
            Vts[(c4+0)*AST + r] = to_tf32(vv.x);
            Vts[(c4+1)*AST + r] = to_tf32(vv.y);
            Vts[(c4+2)*AST + r] = to_tf32(vv.z);
            Vts[(c4+3)*AST + r] = to_tf32(vv.w);
        }
        if (tid < 64) mS[tid] = mask[b*SS + kbase + tid];
        __syncthreads();

        // S = Q K^T  (warp: 16 q-rows x 64 keys)
        float sa[8][4];
#pragma unroll
        for (int fj = 0; fj < 8; fj++)
#pragma unroll
            for (int e = 0; e < 4; e++) sa[fj][e] = 0.f;
#pragma unroll
        for (int ks = 0; ks < 8; ks++) {
            uint32_t bf[8][2];
#pragma unroll
            for (int fj = 0; fj < 8; fj++) {
                const float* bp = &Ks[(fj*8 + g)*AST + ks*8 + tc];
                bf[fj][0] = __float_as_uint(bp[0]);
                bf[fj][1] = __float_as_uint(bp[4]);
            }
#pragma unroll
            for (int fj = 0; fj < 8; fj++)
                MMA_TF32(sa[fj], aq[ks], bf[fj]);
        }

        // mask
#pragma unroll
        for (int fj = 0; fj < 8; fj++) {
            const int c = fj*8 + 2*tc;
            if (mS[c]   == 0) { sa[fj][0] = NEGV; sa[fj][2] = NEGV; }
            if (mS[c+1] == 0) { sa[fj][1] = NEGV; sa[fj][3] = NEGV; }
        }

        // online softmax (rows g and g+8); quad reduction over tc lanes
        float mt0 = -3e38f, mt1 = -3e38f;
#pragma unroll
        for (int fj = 0; fj < 8; fj++) {
            mt0 = fmaxf(mt0, fmaxf(sa[fj][0], sa[fj][1]));
            mt1 = fmaxf(mt1, fmaxf(sa[fj][2], sa[fj][3]));
        }
        mt0 = fmaxf(mt0, __shfl_xor_sync(0xffffffffu, mt0, 1));
        mt0 = fmaxf(mt0, __shfl_xor_sync(0xffffffffu, mt0, 2));
        mt1 = fmaxf(mt1, __shfl_xor_sync(0xffffffffu, mt1, 1));
        mt1 = fmaxf(mt1, __shfl_xor_sync(0xffffffffu, mt1, 2));
        const float mn0 = fmaxf(m0, mt0), mn1 = fmaxf(m1, mt1);
        const float f0 = __expf(m0 - mn0), f1 = __expf(m1 - mn1);
        m0 = mn0; m1 = mn1;

        float rs0 = 0.f, rs1 = 0.f;
#pragma unroll
        for (int fj = 0; fj < 8; fj++) {
            float p0 = __expf(sa[fj][0] - mn0);
            float p1 = __expf(sa[fj][1] - mn0);
            float p2 = __expf(sa[fj][2] - mn1);
            float p3 = __expf(sa[fj][3] - mn1);
            rs0 += p0 + p1; rs1 += p2 + p3;
            *(float2*)&Ps[(w16 + g  )*AST + fj*8 + 2*tc] = make_float2(to_tf32(p0), to_tf32(p1));
            *(float2*)&Ps[(w16 + g+8)*AST + fj*8 + 2*tc] = make_float2(to_tf32(p2), to_tf32(p3));
        }
        rs0 += __shfl_xor_sync(0xffffffffu, rs0, 1);
        rs0 += __shfl_xor_sync(0xffffffffu, rs0, 2);
        rs1 += __shfl_xor_sync(0xffffffffu, rs1, 1);
        rs1 += __shfl_xor_sync(0xffffffffu, rs1, 2);
        l0 = l0 * f0 + rs0;
        l1 = l1 * f1 + rs1;
#pragma unroll
        for (int fj = 0; fj < 8; fj++) {
            acc[fj][0] *= f0; acc[fj][1] *= f0;
            acc[fj][2] *= f1; acc[fj][3] *= f1;
        }
        __syncwarp();

        // O += P Vt  (A = own Ps rows, B = Vts)
#pragma unroll
        for (int ks = 0; ks < 8; ks++) {
            uint32_t ap2[4];
            const float* pp = &Ps[(w16 + g)*AST + ks*8 + tc];
            ap2[0] = __float_as_uint(pp[0]);
            ap2[1] = __float_as_uint(pp[8*AST]);
            ap2[2] = __float_as_uint(pp[4]);
            ap2[3] = __float_as_uint(pp[8*AST + 4]);
#pragma unroll
            for (int fj = 0; fj < 8; fj++) {
                const float* bp = &Vts[(fj*8 + g)*AST + ks*8 + tc];
                uint32_t bf2[2] = { __float_as_uint(bp[0]), __float_as_uint(bp[4]) };
                MMA_TF32(acc[fj], ap2, bf2);
            }
        }
    }

    // write O / l
    const float inv0 = 1.f / l0, inv1 = 1.f / l1;
    float* Og = g_ctx + (size_t)(b*SS)*DDIM + h*DHH;
#pragma unroll
    for (int fj = 0; fj < 8; fj++) {
        const int c = fj*8 + 2*tc;
        *(float2*)(Og + (size_t)(q0 + w16 + g  )*DDIM + c) =
            make_float2(acc[fj][0]*inv0, acc[fj][1]*inv0);
        *(float2*)(Og + (size_t)(q0 + w16 + g+8)*DDIM + c) =
            make_float2(acc[fj][2]*inv1, acc[fj][3]*inv1);
    }
}

// ---------------- LayerNorm over D=1024, one CTA per row --------------------
__global__ __launch_bounds__(256)
void ln_kernel(const float* __restrict__ y, const float* __restrict__ g,
               const float* __restrict__ bta, const int* __restrict__ mask,
               float* __restrict__ out)
{
    const int row = blockIdx.x;
    const int tid = threadIdx.x;
    const float* yr = y + (size_t)row * DDIM;
    __shared__ float red[8];

    float4 xv = *(const float4*)(yr + tid*4);
    float s = xv.x + xv.y + xv.z + xv.w;
#pragma unroll
    for (int o = 16; o > 0; o >>= 1) s += __shfl_xor_sync(0xffffffffu, s, o);
    if ((tid & 31) == 0) red[tid >> 5] = s;
    __syncthreads();
    s = 0.f;
#pragma unroll
    for (int w = 0; w < 8; w++) s += red[w];
    const float mean = s * (1.f / DDIM);

    float dx0 = xv.x - mean, dx1 = xv.y - mean, dx2 = xv.z - mean, dx3 = xv.w - mean;
    float s2 = dx0*dx0 + dx1*dx1 + dx2*dx2 + dx3*dx3;
    __syncthreads();
#pragma unroll
    for (int o = 16; o > 0; o >>= 1) s2 += __shfl_xor_sync(0xffffffffu, s2, o);
    if ((tid & 31) == 0) red[tid >> 5] = s2;
    __syncthreads();
    s2 = 0.f;
#pragma unroll
    for (int w = 0; w < 8; w++) s2 += red[w];
    const float rstd = rsqrtf(s2 * (1.f / DDIM) + 1e-5f);

    const float mv = mask ? (float)mask[row] : 1.f;
    float4 gv = *(const float4*)(g   + tid*4);
    float4 bv = *(const float4*)(bta + tid*4);
    float4 ov;
    ov.x = (dx0 * rstd * gv.x + bv.x) * mv;
    ov.y = (dx1 * rstd * gv.y + bv.y) * mv;
    ov.z = (dx2 * rstd * gv.z + bv.z) * mv;
    ov.w = (dx3 * rstd * gv.w + bv.w) * mv;
    *(float4*)(out + (size_t)row * DDIM + tid*4) = ov;
}

// ---------------- launch --------------------------------------------------
extern "C" void kernel_launch(void* const* d_in, const int* in_sizes, int n_in,
                              void* d_out, int out_size)
{
    const float* x    = (const float*)d_in[0];
    const int*   mask = (const int*)  d_in[1];
    const float* wq = (const float*)d_in[2];  const float* bq = (const float*)d_in[3];
    const float* wk = (const float*)d_in[4];  const float* bk = (const float*)d_in[5];
    const float* wv = (const float*)d_in[6];  const float* bv = (const float*)d_in[7];
    const float* wo = (const float*)d_in[8];  const float* bo = (const float*)d_in[9];
    const float* l1g = (const float*)d_in[10]; const float* l1b = (const float*)d_in[11];
    const float* w1 = (const float*)d_in[12]; const float* b1 = (const float*)d_in[13];
    const float* w2 = (const float*)d_in[14]; const float* b2 = (const float*)d_in[15];
    const float* l2g = (const float*)d_in[16]; const float* l2b = (const float*)d_in[17];

    float *q, *k, *v, *ctx, *y1, *t, *hb, *y2;
    cudaGetSymbolAddress((void**)&q,   g_q);
    cudaGetSymbolAddress((void**)&k,   g_k);
    cudaGetSymbolAddress((void**)&v,   g_v);
    cudaGetSymbolAddress((void**)&ctx, g_ctx);
    cudaGetSymbolAddress((void**)&y1,  g_y1);
    cudaGetSymbolAddress((void**)&t,   g_t);
    cudaGetSymbolAddress((void**)&hb,  g_h);
    cudaGetSymbolAddress((void**)&y2,  g_y2);

    cudaFuncSetAttribute(attn_mma, cudaFuncAttributeMaxDynamicSharedMemorySize, ATTN_SMEM_B);

    dim3 gD(DDIM/128, MM/128);      // 8 x 32
    dim3 gF(FF/128,   MM/128);      // 32 x 32
    dim3 gQKV(DDIM/128, MM/128, 3); // 8 x 32 x 3

    qkv_gemm<<<gQKV, 256>>>(x, wq, bq, wk, bk, wv, bv, q, k, v);

    attn_mma<<<dim3(SS/64, HH, BB), 128, ATTN_SMEM_B>>>(mask);

    mgemm<1><<<gD, 256>>>(ctx, wo, bo, x,       y1, MM, DDIM, DDIM);
    ln_kernel<<<MM, 256>>>(y1, l1g, l1b, nullptr, t);

    mgemm<2><<<gF, 256>>>(t,   w1, b1, nullptr, hb, MM, FF,   DDIM);
    mgemm<1><<<gD, 256>>>(hb,  w2, b2, t,       y2, MM, DDIM, FF);
    ln_kernel<<<MM, 256>>>(y2, l2g, l2b, mask, (float*)d_out);
}

// round 13
// speedup vs baseline: 3.3793x; 1.1468x over previous
#include <cuda_runtime.h>
#include <math.h>
#include <stdint.h>

#define BB   4
#define SS   1024
#define DDIM 1024
#define HH   16
#define DHH  64
#define FF   4096
#define MM   (BB*SS)      // 4096 rows
#define NEGV (-1e20f)

// ---------------- scratch (allocation-free: device globals) ----------------
__device__ float g_q  [MM*DDIM];
__device__ float g_k  [MM*DDIM];
__device__ float g_v  [MM*DDIM];
__device__ float g_ctx[MM*DDIM];
__device__ float g_y1 [MM*DDIM];
__device__ float g_t  [MM*DDIM];
__device__ float g_h  [(size_t)MM*FF];
__device__ float g_y2 [MM*DDIM];

// ---------------- helpers ---------------------------------------------------
__device__ __forceinline__ float to_tf32(float x) {
    float y;
    asm("cvt.rna.tf32.f32 %0, %1;" : "=f"(y) : "f"(x));
    return y;
}
__device__ __forceinline__ uint32_t smem_u32(const void* p) {
    uint32_t a;
    asm("{ .reg .u64 t; cvta.to.shared.u64 t, %1; cvt.u32.u64 %0, t; }"
        : "=r"(a) : "l"(p));
    return a;
}
__device__ __forceinline__ void cpa16(uint32_t dst, const void* src) {
    asm volatile("cp.async.cg.shared.global [%0], [%1], 16;" :: "r"(dst), "l"(src));
}
#define CPA_COMMIT() asm volatile("cp.async.commit_group;" ::: "memory")
#define CPA_WAIT1()  asm volatile("cp.async.wait_group 1;" ::: "memory")
#define CPA_WAIT0()  asm volatile("cp.async.wait_group 0;" ::: "memory")

#define MMA_TF32(d, a, b)                                                      \
    asm volatile("mma.sync.aligned.m16n8k8.row.col.f32.tf32.tf32.f32 "         \
                 "{%0,%1,%2,%3}, {%4,%5,%6,%7}, {%8,%9}, {%0,%1,%2,%3};"       \
                 : "+f"((d)[0]), "+f"((d)[1]), "+f"((d)[2]), "+f"((d)[3])      \
                 : "r"((a)[0]), "r"((a)[1]), "r"((a)[2]), "r"((a)[3]),         \
                   "r"((b)[0]), "r"((b)[1]))

#define SST 20   // smem row stride in floats (conflict-free fragment loads)

// Shared GEMM body: C[M,N] = A[M,K] @ W[N,K]^T + bias (+epi).
// cp.async staging of raw fp32 (mma.tf32 truncates mantissa in HW).
// EPI: 0 = bias, 1 = bias + residual R, 2 = bias + relu
template<int EPI>
__device__ __forceinline__ void mgemm_body(
    const float* __restrict__ A, const float* __restrict__ W,
    const float* __restrict__ bias, const float* __restrict__ R,
    float* __restrict__ C, int M, int N, int K,
    float (&As)[2][128][SST], float (&Bs)[2][128][SST],
    int bm, int bn)
{
    const int tid  = threadIdx.x;
    const int lane = tid & 31;
    const int wid  = tid >> 5;
    const int wm   = wid >> 1;        // 0..3 -> warp M offset *32
    const int wn   = wid & 1;         // 0..1 -> warp N offset *64
    const int g    = lane >> 2;       // 0..7
    const int tc   = lane & 3;        // 0..3

    // staging coords: 512 float4 per tile (128 rows x 16 cols)
    const int f0 = tid,        r0s = f0 >> 2, c0s = (f0 & 3) << 2;
    const int f1 = tid + 256,  r1s = f1 >> 2, c1s = (f1 & 3) << 2;

    const float* Ag0 = A + (size_t)(bm + r0s) * K + c0s;
    const float* Ag1 = A + (size_t)(bm + r1s) * K + c1s;
    const float* Wg0 = W + (size_t)(bn + r0s) * K + c0s;
    const float* Wg1 = W + (size_t)(bn + r1s) * K + c1s;

    const uint32_t aBase = smem_u32(&As[0][0][0]);
    const uint32_t bBase = smem_u32(&Bs[0][0][0]);
    const uint32_t bufStride = 128u * SST * 4u;
    const uint32_t offA0 = (uint32_t)(r0s * SST + c0s) * 4u;
    const uint32_t offA1 = (uint32_t)(r1s * SST + c1s) * 4u;

    float acc[2][8][4];
#pragma unroll
    for (int i = 0; i < 2; i++)
#pragma unroll
        for (int j = 0; j < 8; j++)
#pragma unroll
            for (int e = 0; e < 4; e++) acc[i][j][e] = 0.f;

    // prologue: async-stage chunk 0 into buffer 0
    cpa16(aBase + offA0, Ag0);
    cpa16(aBase + offA1, Ag1);
    cpa16(bBase + offA0, Wg0);
    cpa16(bBase + offA1, Wg1);
    CPA_COMMIT();

    const int nch = K >> 4;
    for (int ch = 0; ch < nch; ch++) {
        const int buf = ch & 1;
        const bool more = (ch + 1) < nch;
        if (more) {
            const int k0 = (ch + 1) << 4;
            const uint32_t bo = (buf ^ 1) * bufStride;
            cpa16(aBase + bo + offA0, Ag0 + k0);
            cpa16(aBase + bo + offA1, Ag1 + k0);
            cpa16(bBase + bo + offA0, Wg0 + k0);
            cpa16(bBase + bo + offA1, Wg1 + k0);
            CPA_COMMIT();
            CPA_WAIT1();
        } else {
            CPA_WAIT0();
        }
        __syncthreads();                       // buf data visible to all warps

#pragma unroll
        for (int kk = 0; kk < 2; kk++) {
            const int k8 = kk * 8;
            uint32_t af[2][4], bf[8][2];
#pragma unroll
            for (int fi = 0; fi < 2; fi++) {
                const float* ap = &As[buf][wm*32 + fi*16 + g][k8 + tc];
                af[fi][0] = __float_as_uint(ap[0]);
                af[fi][1] = __float_as_uint(ap[8*SST]);
                af[fi][2] = __float_as_uint(ap[4]);
                af[fi][3] = __float_as_uint(ap[8*SST + 4]);
            }
#pragma unroll
            for (int fj = 0; fj < 8; fj++) {
                const float* bp = &Bs[buf][wn*64 + fj*8 + g][k8 + tc];
                bf[fj][0] = __float_as_uint(bp[0]);
                bf[fj][1] = __float_as_uint(bp[4]);
            }
#pragma unroll
            for (int fi = 0; fi < 2; fi++)
#pragma unroll
                for (int fj = 0; fj < 8; fj++)
                    MMA_TF32(acc[fi][fj], af[fi], bf[fj]);
        }
        __syncthreads();                       // WAR: next issue overwrites buf^1
    }

    // epilogue: d0,d1 -> (row=g, col=2tc,2tc+1); d2,d3 -> (row=g+8, same)
#pragma unroll
    for (int fi = 0; fi < 2; fi++) {
        const int ra = bm + wm*32 + fi*16 + g;
#pragma unroll
        for (int fj = 0; fj < 8; fj++) {
            const int c = bn + wn*64 + fj*8 + 2*tc;
            const float2 b2 = *(const float2*)(bias + c);
            float x0 = acc[fi][fj][0] + b2.x;
            float x1 = acc[fi][fj][1] + b2.y;
            float x2 = acc[fi][fj][2] + b2.x;
            float x3 = acc[fi][fj][3] + b2.y;
            if (EPI == 2) {
                x0 = fmaxf(x0, 0.f); x1 = fmaxf(x1, 0.f);
                x2 = fmaxf(x2, 0.f); x3 = fmaxf(x3, 0.f);
            }
            if (EPI == 1) {
                const float2 r2a = *(const float2*)(R + (size_t)ra * N + c);
                const float2 r2b = *(const float2*)(R + (size_t)(ra+8) * N + c);
                x0 += r2a.x; x1 += r2a.y; x2 += r2b.x; x3 += r2b.y;
            }
            float2 o0 = make_float2(x0, x1);
            float2 o1 = make_float2(x2, x3);
            *(float2*)(C + (size_t)ra * N + c)     = o0;
            *(float2*)(C + (size_t)(ra+8) * N + c) = o1;
        }
    }
}

template<int EPI>
__global__ __launch_bounds__(256, 2)
void mgemm(const float* __restrict__ A, const float* __restrict__ W,
           const float* __restrict__ bias, const float* __restrict__ R,
           float* __restrict__ C, int M, int N, int K)
{
    __shared__ __align__(16) float As[2][128][SST];
    __shared__ __align__(16) float Bs[2][128][SST];
    mgemm_body<EPI>(A, W, bias, R, C, M, N, K, As, Bs,
                    blockIdx.y * 128, blockIdx.x * 128);
}

// fused QKV: blockIdx.z selects (W, bias, C); one launch = 3x the CTAs.
__global__ __launch_bounds__(256, 2)
void qkv_gemm(const float* __restrict__ A,
              const float* __restrict__ wq, const float* __restrict__ bq,
              const float* __restrict__ wk, const float* __restrict__ bk,
              const float* __restrict__ wv, const float* __restrict__ bv,
              float* __restrict__ q, float* __restrict__ k, float* __restrict__ v)
{
    __shared__ __align__(16) float As[2][128][SST];
    __shared__ __align__(16) float Bs[2][128][SST];
    const int z = blockIdx.z;
    const float* W    = (z == 0) ? wq : (z == 1) ? wk : wv;
    const float* bias = (z == 0) ? bq : (z == 1) ? bk : bv;
    float*       C    = (z == 0) ? q  : (z == 1) ? k  : v;
    mgemm_body<0>(A, W, bias, nullptr, C, MM, DDIM, DDIM, As, Bs,
                  blockIdx.y * 128, blockIdx.x * 128);
}

// ---------------- tf32 mma flash attention ----------------------------------
// CTA: 128 threads (4 warps). Q-tile 64 (16 rows/warp), K-tile 64, DH=64.
// smem stride 68 (== 4 mod 32) -> conflict-free fragment LDS.
#define AST 68
#define ATTN_SMEM_B (3*64*AST*4 + 64*4)

__global__ __launch_bounds__(128)
void attn_mma(const int* __restrict__ mask)
{
    extern __shared__ float smf[];
    float* Ks  = smf;              // 64 x AST  (key x dh), tf32
    float* Vts = Ks  + 64*AST;     // 64 x AST  (dh x key), tf32
    float* Ps  = Vts + 64*AST;     // 64 x AST  (q x key), tf32; also Q staging
    int*   mS  = (int*)(Ps + 64*AST);

    const int q0   = blockIdx.x * 64;
    const int h    = blockIdx.y;
    const int b    = blockIdx.z;
    const int tid  = threadIdx.x;
    const int wid  = tid >> 5, lane = tid & 31;
    const int g    = lane >> 2, tc = lane & 3;
    const int w16  = wid * 16;

    const float* Qg = g_q + (size_t)(b*SS)*DDIM + h*DHH;
    const float* Kg = g_k + (size_t)(b*SS)*DDIM + h*DHH;
    const float* Vg = g_v + (size_t)(b*SS)*DDIM + h*DHH;

    // stage Q (scaled by 1/8, tf32) into Ps region, then load fragments to regs
#pragma unroll
    for (int it = 0; it < 8; it++) {
        int f = tid + 128*it;                 // 1024 float4 = 64 x 64
        int r = f >> 4, c4 = (f & 15) << 2;
        float4 v = *(const float4*)(Qg + (size_t)(q0 + r)*DDIM + c4);
        Ps[r*AST + c4 + 0] = to_tf32(v.x * 0.125f);
        Ps[r*AST + c4 + 1] = to_tf32(v.y * 0.125f);
        Ps[r*AST + c4 + 2] = to_tf32(v.z * 0.125f);
        Ps[r*AST + c4 + 3] = to_tf32(v.w * 0.125f);
    }
    __syncthreads();

    uint32_t aq[8][4];
#pragma unroll
    for (int ks = 0; ks < 8; ks++) {
        const float* ap = &Ps[(w16 + g)*AST + ks*8 + tc];
        aq[ks][0] = __float_as_uint(ap[0]);
        aq[ks][1] = __float_as_uint(ap[8*AST]);
        aq[ks][2] = __float_as_uint(ap[4]);
        aq[ks][3] = __float_as_uint(ap[8*AST + 4]);
    }

    float m0 = -3e38f, m1 = -3e38f, l0 = 0.f, l1 = 0.f;
    float acc[8][4];
#pragma unroll
    for (int fj = 0; fj < 8; fj++)
#pragma unroll
        for (int e = 0; e < 4; e++) acc[fj][e] = 0.f;

    for (int kt = 0; kt < SS/64; kt++) {
        __syncthreads();                      // protect Ks/Vts (and Ps on kt=0)
        const int kbase = kt * 64;
        // stage K (tf32) and V transposed (tf32)
#pragma unroll
        for (int it = 0; it < 8; it++) {
            int f = tid + 128*it;
            int r = f >> 4, c4 = (f & 15) << 2;
            float4 kv = *(const float4*)(Kg + (size_t)(kbase + r)*DDIM + c4);
            Ks[r*AST + c4 + 0] = to_tf32(kv.x);
            Ks[r*AST + c4 + 1] = to_tf32(kv.y);
            Ks[r*AST + c4 + 2] = to_tf32(kv.z);
            Ks[r*AST + c4 + 3] = to_tf32(kv.w);
            float4 vv = *(const float4*)(Vg + (size_t)(kbase + r)*DDIM + c4);
            Vts[(c4+0)*AST + r] = to_tf32(vv.x);
            Vts[(c4+1)*AST + r] = to_tf32(vv.y);
            Vts[(c4+2)*AST + r] = to_tf32(vv.z);
            Vts[(c4+3)*AST + r] = to_tf32(vv.w);
        }
        if (tid < 64) mS[tid] = mask[b*SS + kbase + tid];
        __syncthreads();

        // S = Q K^T  (warp: 16 q-rows x 64 keys)
        float sa[8][4];
#pragma unroll
        for (int fj = 0; fj < 8; fj++)
#pragma unroll
            for (int e = 0; e < 4; e++) sa[fj][e] = 0.f;
#pragma unroll
        for (int ks = 0; ks < 8; ks++) {
            uint32_t bf[8][2];
#pragma unroll
            for (int fj = 0; fj < 8; fj++) {
                const float* bp = &Ks[(fj*8 + g)*AST + ks*8 + tc];
                bf[fj][0] = __float_as_uint(bp[0]);
                bf[fj][1] = __float_as_uint(bp[4]);
            }
#pragma unroll
            for (int fj = 0; fj < 8; fj++)
                MMA_TF32(sa[fj], aq[ks], bf[fj]);
        }

        // mask
#pragma unroll
        for (int fj = 0; fj < 8; fj++) {
            const int c = fj*8 + 2*tc;
            if (mS[c]   == 0) { sa[fj][0] = NEGV; sa[fj][2] = NEGV; }
            if (mS[c+1] == 0) { sa[fj][1] = NEGV; sa[fj][3] = NEGV; }
        }

        // online softmax (rows g and g+8); quad reduction over tc lanes
        float mt0 = -3e38f, mt1 = -3e38f;
#pragma unroll
        for (int fj = 0; fj < 8; fj++) {
            mt0 = fmaxf(mt0, fmaxf(sa[fj][0], sa[fj][1]));
            mt1 = fmaxf(mt1, fmaxf(sa[fj][2], sa[fj][3]));
        }
        mt0 = fmaxf(mt0, __shfl_xor_sync(0xffffffffu, mt0, 1));
        mt0 = fmaxf(mt0, __shfl_xor_sync(0xffffffffu, mt0, 2));
        mt1 = fmaxf(mt1, __shfl_xor_sync(0xffffffffu, mt1, 1));
        mt1 = fmaxf(mt1, __shfl_xor_sync(0xffffffffu, mt1, 2));
        const float mn0 = fmaxf(m0, mt0), mn1 = fmaxf(m1, mt1);
        const float f0 = __expf(m0 - mn0), f1 = __expf(m1 - mn1);
        m0 = mn0; m1 = mn1;

        float rs0 = 0.f, rs1 = 0.f;
#pragma unroll
        for (int fj = 0; fj < 8; fj++) {
            float p0 = __expf(sa[fj][0] - mn0);
            float p1 = __expf(sa[fj][1] - mn0);
            float p2 = __expf(sa[fj][2] - mn1);
            float p3 = __expf(sa[fj][3] - mn1);
            rs0 += p0 + p1; rs1 += p2 + p3;
            *(float2*)&Ps[(w16 + g  )*AST + fj*8 + 2*tc] = make_float2(to_tf32(p0), to_tf32(p1));
            *(float2*)&Ps[(w16 + g+8)*AST + fj*8 + 2*tc] = make_float2(to_tf32(p2), to_tf32(p3));
        }
        rs0 += __shfl_xor_sync(0xffffffffu, rs0, 1);
        rs0 += __shfl_xor_sync(0xffffffffu, rs0, 2);
        rs1 += __shfl_xor_sync(0xffffffffu, rs1, 1);
        rs1 += __shfl_xor_sync(0xffffffffu, rs1, 2);
        l0 = l0 * f0 + rs0;
        l1 = l1 * f1 + rs1;
#pragma unroll
        for (int fj = 0; fj < 8; fj++) {
            acc[fj][0] *= f0; acc[fj][1] *= f0;
            acc[fj][2] *= f1; acc[fj][3] *= f1;
        }
        __syncwarp();

        // O += P Vt  (A = own Ps rows, B = Vts)
#pragma unroll
        for (int ks = 0; ks < 8; ks++) {
            uint32_t ap2[4];
            const float* pp = &Ps[(w16 + g)*AST + ks*8 + tc];
            ap2[0] = __float_as_uint(pp[0]);
            ap2[1] = __float_as_uint(pp[8*AST]);
            ap2[2] = __float_as_uint(pp[4]);
            ap2[3] = __float_as_uint(pp[8*AST + 4]);
#pragma unroll
            for (int fj = 0; fj < 8; fj++) {
                const float* bp = &Vts[(fj*8 + g)*AST + ks*8 + tc];
                uint32_t bf2[2] = { __float_as_uint(bp[0]), __float_as_uint(bp[4]) };
                MMA_TF32(acc[fj], ap2, bf2);
            }
        }
    }

    // write O / l
    const float inv0 = 1.f / l0, inv1 = 1.f / l1;
    float* Og = g_ctx + (size_t)(b*SS)*DDIM + h*DHH;
#pragma unroll
    for (int fj = 0; fj < 8; fj++) {
        const int c = fj*8 + 2*tc;
        *(float2*)(Og + (size_t)(q0 + w16 + g  )*DDIM + c) =
            make_float2(acc[fj][0]*inv0, acc[fj][1]*inv0);
        *(float2*)(Og + (size_t)(q0 + w16 + g+8)*DDIM + c) =
            make_float2(acc[fj][2]*inv1, acc[fj][3]*inv1);
    }
}

// ---------------- LayerNorm over D=1024, one CTA per row --------------------
__global__ __launch_bounds__(256)
void ln_kernel(const float* __restrict__ y, const float* __restrict__ g,
               const float* __restrict__ bta, const int* __restrict__ mask,
               float* __restrict__ out)
{
    const int row = blockIdx.x;
    const int tid = threadIdx.x;
    const float* yr = y + (size_t)row * DDIM;
    __shared__ float red[8];

    float4 xv = *(const float4*)(yr + tid*4);
    float s = xv.x + xv.y + xv.z + xv.w;
#pragma unroll
    for (int o = 16; o > 0; o >>= 1) s += __shfl_xor_sync(0xffffffffu, s, o);
    if ((tid & 31) == 0) red[tid >> 5] = s;
    __syncthreads();
    s = 0.f;
#pragma unroll
    for (int w = 0; w < 8; w++) s += red[w];
    const float mean = s * (1.f / DDIM);

    float dx0 = xv.x - mean, dx1 = xv.y - mean, dx2 = xv.z - mean, dx3 = xv.w - mean;
    float s2 = dx0*dx0 + dx1*dx1 + dx2*dx2 + dx3*dx3;
    __syncthreads();
#pragma unroll
    for (int o = 16; o > 0; o >>= 1) s2 += __shfl_xor_sync(0xffffffffu, s2, o);
    if ((tid & 31) == 0) red[tid >> 5] = s2;
    __syncthreads();
    s2 = 0.f;
#pragma unroll
    for (int w = 0; w < 8; w++) s2 += red[w];
    const float rstd = rsqrtf(s2 * (1.f / DDIM) + 1e-5f);

    const float mv = mask ? (float)mask[row] : 1.f;
    float4 gv = *(const float4*)(g   + tid*4);
    float4 bv = *(const float4*)(bta + tid*4);
    float4 ov;
    ov.x = (dx0 * rstd * gv.x + bv.x) * mv;
    ov.y = (dx1 * rstd * gv.y + bv.y) * mv;
    ov.z = (dx2 * rstd * gv.z + bv.z) * mv;
    ov.w = (dx3 * rstd * gv.w + bv.w) * mv;
    *(float4*)(out + (size_t)row * DDIM + tid*4) = ov;
}

// ---------------- launch --------------------------------------------------
extern "C" void kernel_launch(void* const* d_in, const int* in_sizes, int n_in,
                              void* d_out, int out_size)
{
    const float* x    = (const float*)d_in[0];
    const int*   mask = (const int*)  d_in[1];
    const float* wq = (const float*)d_in[2];  const float* bq = (const float*)d_in[3];
    const float* wk = (const float*)d_in[4];  const float* bk = (const float*)d_in[5];
    const float* wv = (const float*)d_in[6];  const float* bv = (const float*)d_in[7];
    const float* wo = (const float*)d_in[8];  const float* bo = (const float*)d_in[9];
    const float* l1g = (const float*)d_in[10]; const float* l1b = (const float*)d_in[11];
    const float* w1 = (const float*)d_in[12]; const float* b1 = (const float*)d_in[13];
    const float* w2 = (const float*)d_in[14]; const float* b2 = (const float*)d_in[15];
    const float* l2g = (const float*)d_in[16]; const float* l2b = (const float*)d_in[17];

    float *q, *k, *v, *ctx, *y1, *t, *hb, *y2;
    cudaGetSymbolAddress((void**)&q,   g_q);
    cudaGetSymbolAddress((void**)&k,   g_k);
    cudaGetSymbolAddress((void**)&v,   g_v);
    cudaGetSymbolAddress((void**)&ctx, g_ctx);
    cudaGetSymbolAddress((void**)&y1,  g_y1);
    cudaGetSymbolAddress((void**)&t,   g_t);
    cudaGetSymbolAddress((void**)&hb,  g_h);
    cudaGetSymbolAddress((void**)&y2,  g_y2);

    cudaFuncSetAttribute(attn_mma, cudaFuncAttributeMaxDynamicSharedMemorySize, ATTN_SMEM_B);

    dim3 gD(DDIM/128, MM/128);      // 8 x 32
    dim3 gF(FF/128,   MM/128);      // 32 x 32
    dim3 gQKV(DDIM/128, MM/128, 3); // 8 x 32 x 3

    qkv_gemm<<<gQKV, 256>>>(x, wq, bq, wk, bk, wv, bv, q, k, v);

    attn_mma<<<dim3(SS/64, HH, BB), 128, ATTN_SMEM_B>>>(mask);

    mgemm<1><<<gD, 256>>>(ctx, wo, bo, x,       y1, MM, DDIM, DDIM);
    ln_kernel<<<MM, 256>>>(y1, l1g, l1b, nullptr, t);

    mgemm<2><<<gF, 256>>>(t,   w1, b1, nullptr, hb, MM, FF,   DDIM);
    mgemm<1><<<gD, 256>>>(hb,  w2, b2, t,       y2, MM, DDIM, FF);
    ln_kernel<<<MM, 256>>>(y2, l2g, l2b, mask, (float*)d_out);
}